// round 10
// baseline (speedup 1.0000x reference)
#include <cuda_runtime.h>
#include <cuda_fp16.h>
#include <cstdint>

#define D_MODEL 256
#define ARITY 32
#define NDEPTH 15
#define VOCAB 1027
#define BATCH 8192
#define KTOT 8192
#define LN_EPS 1e-5f

// ------------------------- device scratch (no allocs allowed) -----------------
__device__ __align__(16) __half g_TPh[VOCAB * D_MODEL];           // token proj + b (fp16)
__device__ __align__(16) __half g_DPh[ARITY * NDEPTH * D_MODEL];  // depth+idx proj (fp16)
__device__ __align__(16) __half g_WThi[(size_t)D_MODEL * KTOT];   // W child blocks, transposed
__device__ __align__(16) float g_part[(size_t)BATCH * D_MODEL];   // split-K partials (kh=1)
__device__ int g_done;
__device__ int g_flag[128];

// ---------------- convW: convert+transpose W child blocks -> WThi [256 x 8192] -
__global__ __launch_bounds__(256)
void convW_kernel(const float* __restrict__ W) {
    if (threadIdx.x == 0) {
        if (blockIdx.x == 0) g_done = 0;
        if (blockIdx.x < 128) g_flag[blockIdx.x] = 0;
    }
    __shared__ float ws[16][257];
    const int kc = blockIdx.x * 16;
    const int t = threadIdx.x;
#pragma unroll
    for (int r = 0; r < 16; r++) {
        int kg = kc + r;
        ws[r][t] = W[(size_t)(256 + (kg >> 8) * 768 + (kg & 255)) * D_MODEL + t];
    }
    __syncthreads();
    uint32_t hi[8];
#pragma unroll
    for (int p = 0; p < 8; p++) {
        __half2 h = __floats2half2_rn(ws[2 * p][t], ws[2 * p + 1][t]);
        hi[p] = *(uint32_t*)&h;
    }
    uint4* ph = (uint4*)(g_WThi + (size_t)t * KTOT + kc);
    ph[0] = make_uint4(hi[0], hi[1], hi[2], hi[3]);
    ph[1] = make_uint4(hi[4], hi[5], hi[6], hi[7]);
}

// ================================ mega kernel ==================================
// 128 threads/CTA. blocks [0,256): GEMM split-K (mt=b>>1, kh=b&1).
// blocks [256,288): dp   blocks [288,417): tp
#define GEMM_BLOCKS 256
#define DP_BLOCKS 32
#define TP_BLOCKS 129
#define PREP_TOTAL (DP_BLOCKS + TP_BLOCKS)
#define SST 40960
#define BOFF 8192
#define SMEM_BYTES 81920  // 2 stages x 40KB -> 2 CTAs/SM

__device__ __forceinline__ void cpa16(uint32_t s, const void* g) {
    asm volatile("cp.async.cg.shared.global [%0], [%1], 16;" :: "r"(s), "l"(g));
}
__device__ __forceinline__ void ldsm4(uint32_t* r, uint32_t a) {
    asm volatile("ldmatrix.sync.aligned.m8n8.x4.shared.b16 {%0,%1,%2,%3}, [%4];"
                 : "=r"(r[0]), "=r"(r[1]), "=r"(r[2]), "=r"(r[3]) : "r"(a));
}
__device__ __forceinline__ void mma_fp16(float* c, const uint32_t* a, const uint32_t* b) {
    asm volatile(
        "mma.sync.aligned.m16n8k16.row.col.f32.f16.f16.f32 "
        "{%0,%1,%2,%3}, {%4,%5,%6,%7}, {%8,%9}, {%0,%1,%2,%3};"
        : "+f"(c[0]), "+f"(c[1]), "+f"(c[2]), "+f"(c[3])
        : "r"(a[0]), "r"(a[1]), "r"(a[2]), "r"(a[3]), "r"(b[0]), "r"(b[1]));
}
__device__ __forceinline__ int ld_acq(const int* p) {
    int v;
    asm volatile("ld.acquire.gpu.s32 %0, [%1];" : "=r"(v) : "l"(p));
    return v;
}
__device__ __forceinline__ void add_half8(float* hb, uint4 v) {
    const __half2* q = (const __half2*)&v;
#pragma unroll
    for (int p = 0; p < 4; p++) {
        float2 f = __half22float2(q[p]);
        hb[2 * p] += f.x;
        hb[2 * p + 1] += f.y;
    }
}

__device__ void gemm_body(char* smem, int mt, int kh, const float* __restrict__ ce,
                          const int* __restrict__ nid, const int* __restrict__ cdep,
                          const float* __restrict__ ln_g, const float* __restrict__ ln_b,
                          float* __restrict__ out) {
    uint32_t sb;
    asm("{ .reg .u64 t; cvta.to.shared.u64 t, %1; cvt.u32.u64 %0, t; }"
        : "=r"(sb) : "l"(smem));
    const int t = threadIdx.x;
    const int lane = t & 31, wn = t >> 5;   // 4 warps; warp tile 64m x 64n
    const int m0 = mt * 64;
    const int c0 = kh * 64;

    // A ldsm addressing: 4 frags (i) cover rows 0..63
    const int arow_base = (lane & 7) + ((lane >> 3) & 1) * 8;
    const uint32_t axor = (uint32_t)((arow_base & 7) << 4);
    const uint32_t khA = (uint32_t)((lane >> 4) * 16);
    // B ldsm addressing: warp wn owns n-rows [wn*64, wn*64+64)
    const int brow_base = wn * 64 + (lane & 7) + ((lane >> 4) & 1) * 8;
    const uint32_t bxor = (uint32_t)((lane & 7) << 4);
    const uint32_t khB = (uint32_t)(((lane >> 3) & 1) * 16);
    uint32_t arowb[4], browb[4];
#pragma unroll
    for (int i = 0; i < 4; i++) arowb[i] = (uint32_t)(arow_base + i * 16) * 128;
#pragma unroll
    for (int jp = 0; jp < 4; jp++) browb[jp] = (uint32_t)(brow_base + jp * 16) * 128;

    // A LDG/STS mapping: row = t>>1 (0..63), k-half = t&1 (32 floats)
    const int prow = t >> 1, phalf = t & 1;
    const uint32_t prx = (uint32_t)((prow & 7) << 4);
    // B cp.async mapping: 256 rows x 8 chunks / 128 threads = 16 each
    const int bro = t >> 3, bo = t & 7;

    float acc[4][8][4];
#pragma unroll
    for (int i = 0; i < 4; i++)
#pragma unroll
        for (int j = 0; j < 8; j++)
#pragma unroll
            for (int q = 0; q < 4; q++) acc[i][j][q] = 0.f;

    float4 av[8];

    auto loadB = [&](int s, int buf) {
        const size_t kg = (size_t)(c0 + s) * 64;
        const uint32_t db = sb + buf * SST + BOFF;
#pragma unroll
        for (int i = 0; i < 16; i++) {
            int row = bro + i * 16;
            uint32_t so = (uint32_t)row * 128 +
                          (((uint32_t)bo * 16) ^ ((uint32_t)(row & 7) << 4));
            cpa16(db + so, g_WThi + (size_t)row * KTOT + kg + bo * 8);
        }
    };
    auto loadA = [&](int s) {
        const int c = c0 + s;
        const int a = c >> 2, kin = (c & 3) * 64;
        const float* p = ce + ((size_t)a * BATCH + m0 + prow) * D_MODEL + kin + phalf * 32;
#pragma unroll
        for (int q = 0; q < 8; q++) av[q] = *(const float4*)(p + q * 4);
    };
    auto stsA = [&](int buf) {
        const uint32_t da = sb + buf * SST;
        const uint32_t rbase = (uint32_t)prow * 128;
        uint32_t hv[16];
#pragma unroll
        for (int q = 0; q < 8; q++) {
            __half2 h01 = __floats2half2_rn(av[q].x, av[q].y);
            __half2 h23 = __floats2half2_rn(av[q].z, av[q].w);
            hv[2 * q]     = *(uint32_t*)&h01;
            hv[2 * q + 1] = *(uint32_t*)&h23;
        }
#pragma unroll
        for (int q = 0; q < 4; q++) {
            uint32_t off = rbase + (((uint32_t)(phalf * 64 + q * 16)) ^ prx);
            asm volatile("st.shared.v4.b32 [%0], {%1,%2,%3,%4};"
                         :: "r"(da + off), "r"(hv[4 * q]), "r"(hv[4 * q + 1]),
                            "r"(hv[4 * q + 2]), "r"(hv[4 * q + 3]));
        }
    };
    auto compute = [&](int buf) {
        const uint32_t SA = sb + buf * SST;
        const uint32_t SB = sb + buf * SST + BOFF;
#pragma unroll
        for (int kk = 0; kk < 4; kk++) {
            uint32_t ah[4][4], bh[4][4];
            const uint32_t ka = ((uint32_t)(kk * 32) + khA) ^ axor;
            const uint32_t kb = ((uint32_t)(kk * 32) + khB) ^ bxor;
#pragma unroll
            for (int i = 0; i < 4; i++) ldsm4(ah[i], SA + arowb[i] + ka);
#pragma unroll
            for (int jp = 0; jp < 4; jp++) ldsm4(bh[jp], SB + browb[jp] + kb);
#pragma unroll
            for (int i = 0; i < 4; i++)
#pragma unroll
                for (int j = 0; j < 8; j++)
                    mma_fp16(acc[i][j], ah[i], &bh[j >> 1][(j & 1) * 2]);
        }
    };

    // prologue
    loadB(0, 0);
    loadA(0);
    stsA(0);
    asm volatile("cp.async.commit_group;" ::: "memory");
    asm volatile("cp.async.wait_group 0;" ::: "memory");
    __syncthreads();

    for (int s = 0; s < 64; s++) {
        const int buf = s & 1, nxt = buf ^ 1;
        if (s + 1 < 64) { loadB(s + 1, nxt); loadA(s + 1); }
        compute(buf);
        if (s + 1 < 64) {
            stsA(nxt);
            asm volatile("cp.async.commit_group;" ::: "memory");
            asm volatile("cp.async.wait_group 0;" ::: "memory");
        }
        __syncthreads();
    }

    if (kh == 1) {
        // ---------------- write partial, raise flag ----------------------------
#pragma unroll
        for (int i = 0; i < 4; i++)
#pragma unroll
            for (int j = 0; j < 8; j++) {
                const int r = m0 + i * 16 + (lane >> 2);
                const int c = wn * 64 + j * 8 + (lane & 3) * 2;
                *(float2*)(g_part + (size_t)r * D_MODEL + c) =
                    make_float2(acc[i][j][0], acc[i][j][1]);
                *(float2*)(g_part + (size_t)(r + 8) * D_MODEL + c) =
                    make_float2(acc[i][j][2], acc[i][j][3]);
            }
        __syncthreads();
        __threadfence();
        if (t == 0) atomicAdd(&g_flag[mt], 1);
        return;
    }

    // ---------------- kh==0: fused epilogue ------------------------------------
    float* sh = (float*)smem;  // [64][260]
    {
        const int rb = lane >> 2;
        const int cbase = wn * 64 + (lane & 3) * 2;
#pragma unroll
        for (int i = 0; i < 4; i++)
#pragma unroll
            for (int j = 0; j < 8; j++) {
                const int rr = i * 16 + rb;
                const int cc = cbase + j * 8;
                sh[rr * 260 + cc]           = acc[i][j][0];
                sh[rr * 260 + cc + 1]       = acc[i][j][1];
                sh[(rr + 8) * 260 + cc]     = acc[i][j][2];
                sh[(rr + 8) * 260 + cc + 1] = acc[i][j][3];
            }
    }
    // wait for prep tables and the other K-half's partial
    if (t == 0) {
        while (ld_acq(&g_done) < PREP_TOTAL) __nanosleep(64);
        while (ld_acq(&g_flag[mt]) == 0) __nanosleep(64);
    }
    __syncthreads();

    // warp wn handles rows [wn*16, wn*16+16)
    const int cb = lane * 8;
    float4 gg0 = *(const float4*)(ln_g + cb), gg1 = *(const float4*)(ln_g + cb + 4);
    float4 bb0 = *(const float4*)(ln_b + cb), bb1 = *(const float4*)(ln_b + cb + 4);
    const float gj[8] = {gg0.x, gg0.y, gg0.z, gg0.w, gg1.x, gg1.y, gg1.z, gg1.w};
    const float lj[8] = {bb0.x, bb0.y, bb0.z, bb0.w, bb1.x, bb1.y, bb1.z, bb1.w};

    int dvals[16];
#pragma unroll
    for (int q = 0; q < 16; q++)
        dvals[q] = cdep[(size_t)lane * BATCH + (m0 + wn * 16 + q)];

#pragma unroll 2
    for (int q = 0; q < 16; q++) {
        const int r = m0 + wn * 16 + q;
        float hb[8];
        const float* sp = sh + (wn * 16 + q) * 260 + cb;
#pragma unroll
        for (int x = 0; x < 8; x++) hb[x] = sp[x];

        // add the other K-half partial
        {
            float4 p0 = *(const float4*)(g_part + (size_t)r * D_MODEL + cb);
            float4 p1 = *(const float4*)(g_part + (size_t)r * D_MODEL + cb + 4);
            hb[0] += p0.x; hb[1] += p0.y; hb[2] += p0.z; hb[3] += p0.w;
            hb[4] += p1.x; hb[5] += p1.y; hb[6] += p1.z; hb[7] += p1.w;
        }

        const int tk = nid[r];
        add_half8(hb, *(const uint4*)(g_TPh + tk * D_MODEL + cb));
#pragma unroll
        for (int a = 0; a < ARITY; a++) {
            const int d = __shfl_sync(0xFFFFFFFFu, dvals[q], a);
            add_half8(hb, *(const uint4*)(g_DPh + ((a * NDEPTH + d) << 8) + cb));
        }

        float s = 0.f, ss = 0.f;
#pragma unroll
        for (int x = 0; x < 8; x++) {
            hb[x] = fmaxf(hb[x], 0.f);
            s += hb[x];
            ss = fmaf(hb[x], hb[x], ss);
        }
#pragma unroll
        for (int o = 16; o > 0; o >>= 1) {
            s  += __shfl_xor_sync(0xFFFFFFFFu, s, o);
            ss += __shfl_xor_sync(0xFFFFFFFFu, ss, o);
        }
        const float mu = s * (1.f / 256.f);
        const float rs = rsqrtf(ss * (1.f / 256.f) - mu * mu + LN_EPS);

        float4 o0, o1;
        o0.x = (hb[0] - mu) * rs * gj[0] + lj[0];
        o0.y = (hb[1] - mu) * rs * gj[1] + lj[1];
        o0.z = (hb[2] - mu) * rs * gj[2] + lj[2];
        o0.w = (hb[3] - mu) * rs * gj[3] + lj[3];
        o1.x = (hb[4] - mu) * rs * gj[4] + lj[4];
        o1.y = (hb[5] - mu) * rs * gj[5] + lj[5];
        o1.z = (hb[6] - mu) * rs * gj[6] + lj[6];
        o1.w = (hb[7] - mu) * rs * gj[7] + lj[7];
        *(float4*)(out + (size_t)r * D_MODEL + cb)     = o0;
        *(float4*)(out + (size_t)r * D_MODEL + cb + 4) = o1;
    }
}

// ---------------- prep bodies (128 threads: two column halves) -----------------
__device__ void dp_body(int a, char* sbuf,
                        const float* __restrict__ depth_emb,
                        const float* __restrict__ idx_emb,
                        const float* __restrict__ W) {
    float* de_s = (float*)sbuf;              // 15*256
    float* ie_s = de_s + NDEPTH * D_MODEL;   // 256
    const int t = threadIdx.x;
    for (int i = t; i < NDEPTH * D_MODEL; i += 128) de_s[i] = depth_emb[i];
    ie_s[t] = idx_emb[a * D_MODEL + t];
    ie_s[t + 128] = idx_emb[a * D_MODEL + t + 128];
    __syncthreads();

#pragma unroll
    for (int h = 0; h < 2; h++) {
        const int j = t + h * 128;
        float acc[NDEPTH];
#pragma unroll
        for (int m = 0; m < NDEPTH; m++) acc[m] = 0.f;
        float acci = 0.f;
        const float* Wde = W + (size_t)(512 + a * 768) * D_MODEL + j;
        const float* Wie = W + (size_t)(768 + a * 768) * D_MODEL + j;
#pragma unroll 8
        for (int k = 0; k < D_MODEL; k++) {
            float wde = Wde[k * D_MODEL];
            float wie = Wie[k * D_MODEL];
            acci = fmaf(ie_s[k], wie, acci);
#pragma unroll
            for (int m = 0; m < NDEPTH; m++)
                acc[m] = fmaf(de_s[m * D_MODEL + k], wde, acc[m]);
        }
#pragma unroll
        for (int m = 0; m < NDEPTH; m++)
            g_DPh[(a * NDEPTH + m) * D_MODEL + j] = __float2half_rn(acc[m] + acci);
    }
    __syncthreads();
    __threadfence();
    if (threadIdx.x == 0) atomicAdd(&g_done, 1);
}

__device__ void tp_body(int blk, char* sbuf,
                        const float* __restrict__ token_emb,
                        const float* __restrict__ W,
                        const float* __restrict__ bvec) {
    float* te_s = (float*)sbuf;  // 8*256
    const int v0 = blk * 8;
    const int t = threadIdx.x;
#pragma unroll
    for (int m = 0; m < 8; m++) {
        int v = v0 + m;
        te_s[m * D_MODEL + t]       = (v < VOCAB) ? token_emb[v * D_MODEL + t] : 0.f;
        te_s[m * D_MODEL + t + 128] = (v < VOCAB) ? token_emb[v * D_MODEL + t + 128] : 0.f;
    }
    __syncthreads();
#pragma unroll
    for (int h = 0; h < 2; h++) {
        const int j = t + h * 128;
        float acc[8];
        float bj = bvec[j];
#pragma unroll
        for (int m = 0; m < 8; m++) acc[m] = bj;
        const float* Wt = W + j;
#pragma unroll 8
        for (int k = 0; k < D_MODEL; k++) {
            float w = Wt[k * D_MODEL];
#pragma unroll
            for (int m = 0; m < 8; m++)
                acc[m] = fmaf(te_s[m * D_MODEL + k], w, acc[m]);
        }
#pragma unroll
        for (int m = 0; m < 8; m++) {
            int v = v0 + m;
            if (v < VOCAB) g_TPh[v * D_MODEL + j] = __float2half_rn(acc[m]);
        }
    }
    __syncthreads();
    __threadfence();
    if (threadIdx.x == 0) atomicAdd(&g_done, 1);
}

__global__ __launch_bounds__(128, 2)
void mega_kernel(const float* __restrict__ ce,
                 const float* __restrict__ depth_emb,
                 const float* __restrict__ idx_emb,
                 const float* __restrict__ token_emb,
                 const float* __restrict__ W,
                 const float* __restrict__ bvec,
                 const int* __restrict__ nid,
                 const int* __restrict__ cdep,
                 const float* __restrict__ ln_g,
                 const float* __restrict__ ln_b,
                 float* __restrict__ out) {
    extern __shared__ char smem[];
    const int b = blockIdx.x;
    if (b < GEMM_BLOCKS) gemm_body(smem, b >> 1, b & 1, ce, nid, cdep, ln_g, ln_b, out);
    else if (b < GEMM_BLOCKS + DP_BLOCKS) dp_body(b - GEMM_BLOCKS, smem, depth_emb, idx_emb, W);
    else tp_body(b - GEMM_BLOCKS - DP_BLOCKS, smem, token_emb, W, bvec);
}

// --------------------------------- launch -------------------------------------
extern "C" void kernel_launch(void* const* d_in, const int* in_sizes, int n_in,
                              void* d_out, int out_size) {
    const int*   nid          = (const int*)d_in[0];
    const float* child_embs   = (const float*)d_in[1];
    const int*   child_depths = (const int*)d_in[2];
    const float* token_emb    = (const float*)d_in[3];
    const float* depth_emb    = (const float*)d_in[4];
    const float* idx_emb      = (const float*)d_in[5];
    const float* W            = (const float*)d_in[6];
    const float* bvec         = (const float*)d_in[7];
    const float* ln_g         = (const float*)d_in[8];
    const float* ln_b         = (const float*)d_in[9];
    float* out = (float*)d_out;

    cudaFuncSetAttribute(mega_kernel, cudaFuncAttributeMaxDynamicSharedMemorySize, SMEM_BYTES);

    convW_kernel<<<KTOT / 16, 256>>>(W);
    mega_kernel<<<GEMM_BLOCKS + DP_BLOCKS + TP_BLOCKS, 128, SMEM_BYTES>>>(
        child_embs, depth_emb, idx_emb, token_emb, W, bvec,
        nid, child_depths, ln_g, ln_b, out);
}

// round 11
// speedup vs baseline: 1.2095x; 1.2095x over previous
#include <cuda_runtime.h>
#include <cuda_fp16.h>
#include <cstdint>

#define D_MODEL 256
#define ARITY 32
#define NDEPTH 15
#define VOCAB 1027
#define BATCH 8192
#define KTOT 8192
#define LN_EPS 1e-5f

// ------------------------- device scratch (no allocs allowed) -----------------
__device__ __align__(16) __half g_TPh[VOCAB * D_MODEL];           // token proj + b (fp16)
__device__ __align__(16) __half g_DPh[ARITY * NDEPTH * D_MODEL];  // depth+idx proj (fp16)
__device__ __align__(16) __half g_WThi[(size_t)D_MODEL * KTOT];   // W child blocks, transposed
__device__ __align__(16) float g_part[(size_t)BATCH * D_MODEL];   // split-K partials (kh=1)
__device__ int g_done;
__device__ int g_flag[128];

// ---------------- convW: convert+transpose W child blocks -> WThi [256 x 8192] -
__global__ __launch_bounds__(256)
void convW_kernel(const float* __restrict__ W) {
    if (threadIdx.x == 0) {
        if (blockIdx.x == 0) g_done = 0;
        if (blockIdx.x < 128) g_flag[blockIdx.x] = 0;
    }
    __shared__ float ws[16][257];
    const int kc = blockIdx.x * 16;
    const int t = threadIdx.x;
#pragma unroll
    for (int r = 0; r < 16; r++) {
        int kg = kc + r;
        ws[r][t] = W[(size_t)(256 + (kg >> 8) * 768 + (kg & 255)) * D_MODEL + t];
    }
    __syncthreads();
    uint32_t hi[8];
#pragma unroll
    for (int p = 0; p < 8; p++) {
        __half2 h = __floats2half2_rn(ws[2 * p][t], ws[2 * p + 1][t]);
        hi[p] = *(uint32_t*)&h;
    }
    uint4* ph = (uint4*)(g_WThi + (size_t)t * KTOT + kc);
    ph[0] = make_uint4(hi[0], hi[1], hi[2], hi[3]);
    ph[1] = make_uint4(hi[4], hi[5], hi[6], hi[7]);
}

// ================================ mega kernel ==================================
// 256 threads/CTA. blocks [0,256): GEMM split-K (mt=b>>1, kh=b&1).
// blocks [256,272): dp (2 arities each)   blocks [272,296): tp (48 rows each)
// grid = 296 == resident capacity (2 CTAs/SM x 148 SMs) -> no straggler tail.
#define GEMM_BLOCKS 256
#define DP_BLOCKS 16
#define TP_BLOCKS 24
#define PREP_TOTAL (DP_BLOCKS + TP_BLOCKS)
#define SST 40960
#define BOFF 8192
#define SMEM_BYTES 81920  // 2 stages x 40KB -> 2 CTAs/SM

__device__ __forceinline__ void cpa16(uint32_t s, const void* g) {
    asm volatile("cp.async.cg.shared.global [%0], [%1], 16;" :: "r"(s), "l"(g));
}
__device__ __forceinline__ void ldsm4(uint32_t* r, uint32_t a) {
    asm volatile("ldmatrix.sync.aligned.m8n8.x4.shared.b16 {%0,%1,%2,%3}, [%4];"
                 : "=r"(r[0]), "=r"(r[1]), "=r"(r[2]), "=r"(r[3]) : "r"(a));
}
__device__ __forceinline__ void mma_fp16(float* c, const uint32_t* a, const uint32_t* b) {
    asm volatile(
        "mma.sync.aligned.m16n8k16.row.col.f32.f16.f16.f32 "
        "{%0,%1,%2,%3}, {%4,%5,%6,%7}, {%8,%9}, {%0,%1,%2,%3};"
        : "+f"(c[0]), "+f"(c[1]), "+f"(c[2]), "+f"(c[3])
        : "r"(a[0]), "r"(a[1]), "r"(a[2]), "r"(a[3]), "r"(b[0]), "r"(b[1]));
}
__device__ __forceinline__ int ld_acq(const int* p) {
    int v;
    asm volatile("ld.acquire.gpu.s32 %0, [%1];" : "=r"(v) : "l"(p));
    return v;
}
__device__ __forceinline__ void add_half8(float* hb, uint4 v) {
    const __half2* q = (const __half2*)&v;
#pragma unroll
    for (int p = 0; p < 4; p++) {
        float2 f = __half22float2(q[p]);
        hb[2 * p] += f.x;
        hb[2 * p + 1] += f.y;
    }
}

__device__ void gemm_body(char* smem, int mt, int kh, const float* __restrict__ ce,
                          const int* __restrict__ nid, const int* __restrict__ cdep,
                          const float* __restrict__ ln_g, const float* __restrict__ ln_b,
                          float* __restrict__ out) {
    uint32_t sb;
    asm("{ .reg .u64 t; cvta.to.shared.u64 t, %1; cvt.u32.u64 %0, t; }"
        : "=r"(sb) : "l"(smem));
    const int t = threadIdx.x;
    const int lane = t & 31, w = t >> 5;
    const int wm = w & 1, wn = w >> 1;     // 2 x 4 warps; warp tile 32 x 64
    const int m0 = mt * 64;
    const int c0 = kh * 64;

    // A ldsm addressing
    const int arow0 = wm * 32 + (lane & 7) + ((lane >> 3) & 1) * 8;
    const uint32_t axor = (uint32_t)((arow0 & 7) << 4);
    const uint32_t khA = (uint32_t)((lane >> 4) * 16);
    // B ldsm addressing
    const int brow0 = wn * 64 + (lane & 7) + ((lane >> 4) & 1) * 8;
    const uint32_t bxor = (uint32_t)((lane & 7) << 4);
    const uint32_t khB = (uint32_t)(((lane >> 3) & 1) * 16);
    uint32_t arowb[2], browb[4];
#pragma unroll
    for (int i = 0; i < 2; i++) arowb[i] = (uint32_t)(arow0 + i * 16) * 128;
#pragma unroll
    for (int jp = 0; jp < 4; jp++) browb[jp] = (uint32_t)(brow0 + jp * 16) * 128;

    // A LDG/STS mapping
    const int prow = t >> 2, pcg = t & 3;
    const uint32_t prx = (uint32_t)((prow & 7) << 4);
    // B cp.async mapping
    const int bro = t >> 3, bo = t & 7;

    float acc[2][8][4];
#pragma unroll
    for (int i = 0; i < 2; i++)
#pragma unroll
        for (int j = 0; j < 8; j++)
#pragma unroll
            for (int q = 0; q < 4; q++) acc[i][j][q] = 0.f;

    float4 av[4];

    auto loadB = [&](int s, int buf) {
        const size_t kg = (size_t)(c0 + s) * 64;
        const uint32_t db = sb + buf * SST + BOFF;
#pragma unroll
        for (int i = 0; i < 8; i++) {
            int row = bro + i * 32;
            uint32_t so = (uint32_t)row * 128 +
                          (((uint32_t)bo * 16) ^ ((uint32_t)(row & 7) << 4));
            cpa16(db + so, g_WThi + (size_t)row * KTOT + kg + bo * 8);
        }
    };
    auto loadA = [&](int s) {
        const int c = c0 + s;
        const int a = c >> 2, kin = (c & 3) * 64;
        const float* p = ce + ((size_t)a * BATCH + m0 + prow) * D_MODEL + kin + pcg * 16;
#pragma unroll
        for (int q = 0; q < 4; q++) av[q] = *(const float4*)(p + q * 4);
    };
    auto stsA = [&](int buf) {
        const uint32_t da = sb + buf * SST;
        const uint32_t rbase = (uint32_t)prow * 128;
        uint32_t hv[8];
#pragma unroll
        for (int q = 0; q < 4; q++) {
            __half2 h01 = __floats2half2_rn(av[q].x, av[q].y);
            __half2 h23 = __floats2half2_rn(av[q].z, av[q].w);
            hv[2 * q]     = *(uint32_t*)&h01;
            hv[2 * q + 1] = *(uint32_t*)&h23;
        }
#pragma unroll
        for (int q = 0; q < 2; q++) {
            uint32_t off = rbase + (((uint32_t)(pcg * 32 + q * 16)) ^ prx);
            asm volatile("st.shared.v4.b32 [%0], {%1,%2,%3,%4};"
                         :: "r"(da + off), "r"(hv[4 * q]), "r"(hv[4 * q + 1]),
                            "r"(hv[4 * q + 2]), "r"(hv[4 * q + 3]));
        }
    };
    auto compute = [&](int buf) {
        const uint32_t SA = sb + buf * SST;
        const uint32_t SB = sb + buf * SST + BOFF;
#pragma unroll
        for (int kk = 0; kk < 4; kk++) {
            uint32_t ah[2][4], bh[4][4];
            const uint32_t ka = ((uint32_t)(kk * 32) + khA) ^ axor;
            const uint32_t kb = ((uint32_t)(kk * 32) + khB) ^ bxor;
#pragma unroll
            for (int i = 0; i < 2; i++) ldsm4(ah[i], SA + arowb[i] + ka);
#pragma unroll
            for (int jp = 0; jp < 4; jp++) ldsm4(bh[jp], SB + browb[jp] + kb);
#pragma unroll
            for (int i = 0; i < 2; i++)
#pragma unroll
                for (int j = 0; j < 8; j++)
                    mma_fp16(acc[i][j], ah[i], &bh[j >> 1][(j & 1) * 2]);
        }
    };

    // prologue
    loadB(0, 0);
    loadA(0);
    stsA(0);
    asm volatile("cp.async.commit_group;" ::: "memory");
    asm volatile("cp.async.wait_group 0;" ::: "memory");
    __syncthreads();

    for (int s = 0; s < 64; s++) {
        const int buf = s & 1, nxt = buf ^ 1;
        if (s + 1 < 64) { loadB(s + 1, nxt); loadA(s + 1); }
        compute(buf);
        if (s + 1 < 64) {
            stsA(nxt);
            asm volatile("cp.async.commit_group;" ::: "memory");
            asm volatile("cp.async.wait_group 0;" ::: "memory");
        }
        __syncthreads();
    }

    if (kh == 1) {
        // ---------------- write partial, raise flag ----------------------------
#pragma unroll
        for (int i = 0; i < 2; i++)
#pragma unroll
            for (int j = 0; j < 8; j++) {
                const int r = m0 + wm * 32 + i * 16 + (lane >> 2);
                const int c = wn * 64 + j * 8 + (lane & 3) * 2;
                *(float2*)(g_part + (size_t)r * D_MODEL + c) =
                    make_float2(acc[i][j][0], acc[i][j][1]);
                *(float2*)(g_part + (size_t)(r + 8) * D_MODEL + c) =
                    make_float2(acc[i][j][2], acc[i][j][3]);
            }
        __syncthreads();
        __threadfence();
        if (t == 0) atomicAdd(&g_flag[mt], 1);
        return;
    }

    // ---------------- kh==0: fused epilogue ------------------------------------
    float* sh = (float*)smem;  // [64][260]
    {
        const int rb = wm * 32 + (lane >> 2);
        const int cbase = wn * 64 + (lane & 3) * 2;
#pragma unroll
        for (int i = 0; i < 2; i++)
#pragma unroll
            for (int j = 0; j < 8; j++) {
                const int rr = rb + i * 16;
                const int cc = cbase + j * 8;
                sh[rr * 260 + cc]           = acc[i][j][0];
                sh[rr * 260 + cc + 1]       = acc[i][j][1];
                sh[(rr + 8) * 260 + cc]     = acc[i][j][2];
                sh[(rr + 8) * 260 + cc + 1] = acc[i][j][3];
            }
    }
    // wait for prep tables and the other K-half's partial
    if (t == 0) {
        while (ld_acq(&g_done) < PREP_TOTAL) __nanosleep(64);
        while (ld_acq(&g_flag[mt]) == 0) __nanosleep(64);
    }
    __syncthreads();

    // warp w handles rows [w*8, w*8+8)
    const int cb = lane * 8;
    float4 gg0 = *(const float4*)(ln_g + cb), gg1 = *(const float4*)(ln_g + cb + 4);
    float4 bb0 = *(const float4*)(ln_b + cb), bb1 = *(const float4*)(ln_b + cb + 4);
    const float gj[8] = {gg0.x, gg0.y, gg0.z, gg0.w, gg1.x, gg1.y, gg1.z, gg1.w};
    const float lj[8] = {bb0.x, bb0.y, bb0.z, bb0.w, bb1.x, bb1.y, bb1.z, bb1.w};

    int dvals[8];
#pragma unroll
    for (int q = 0; q < 8; q++)
        dvals[q] = cdep[(size_t)lane * BATCH + (m0 + w * 8 + q)];

#pragma unroll 2
    for (int q = 0; q < 8; q++) {
        const int r = m0 + w * 8 + q;
        float hb[8];
        const float* sp = sh + (w * 8 + q) * 260 + cb;
#pragma unroll
        for (int x = 0; x < 8; x++) hb[x] = sp[x];

        // add the other K-half partial
        {
            float4 p0 = *(const float4*)(g_part + (size_t)r * D_MODEL + cb);
            float4 p1 = *(const float4*)(g_part + (size_t)r * D_MODEL + cb + 4);
            hb[0] += p0.x; hb[1] += p0.y; hb[2] += p0.z; hb[3] += p0.w;
            hb[4] += p1.x; hb[5] += p1.y; hb[6] += p1.z; hb[7] += p1.w;
        }

        const int tk = nid[r];
        add_half8(hb, *(const uint4*)(g_TPh + tk * D_MODEL + cb));
#pragma unroll
        for (int a = 0; a < ARITY; a++) {
            const int d = __shfl_sync(0xFFFFFFFFu, dvals[q], a);
            add_half8(hb, *(const uint4*)(g_DPh + ((a * NDEPTH + d) << 8) + cb));
        }

        float s = 0.f, ss = 0.f;
#pragma unroll
        for (int x = 0; x < 8; x++) {
            hb[x] = fmaxf(hb[x], 0.f);
            s += hb[x];
            ss = fmaf(hb[x], hb[x], ss);
        }
#pragma unroll
        for (int o = 16; o > 0; o >>= 1) {
            s  += __shfl_xor_sync(0xFFFFFFFFu, s, o);
            ss += __shfl_xor_sync(0xFFFFFFFFu, ss, o);
        }
        const float mu = s * (1.f / 256.f);
        const float rs = rsqrtf(ss * (1.f / 256.f) - mu * mu + LN_EPS);

        float4 o0, o1;
        o0.x = (hb[0] - mu) * rs * gj[0] + lj[0];
        o0.y = (hb[1] - mu) * rs * gj[1] + lj[1];
        o0.z = (hb[2] - mu) * rs * gj[2] + lj[2];
        o0.w = (hb[3] - mu) * rs * gj[3] + lj[3];
        o1.x = (hb[4] - mu) * rs * gj[4] + lj[4];
        o1.y = (hb[5] - mu) * rs * gj[5] + lj[5];
        o1.z = (hb[6] - mu) * rs * gj[6] + lj[6];
        o1.w = (hb[7] - mu) * rs * gj[7] + lj[7];
        *(float4*)(out + (size_t)r * D_MODEL + cb)     = o0;
        *(float4*)(out + (size_t)r * D_MODEL + cb + 4) = o1;
    }
}

// ---------------- prep bodies (256 threads; packed into few blocks) ------------
__device__ void dp_body(int blk, char* sbuf,
                        const float* __restrict__ depth_emb,
                        const float* __restrict__ idx_emb,
                        const float* __restrict__ W) {
    float* de_s = (float*)sbuf;              // 15*256
    float* ie_s = de_s + NDEPTH * D_MODEL;   // 256
    const int j = threadIdx.x;
    for (int i = j; i < NDEPTH * D_MODEL; i += 256) de_s[i] = depth_emb[i];
    __syncthreads();

#pragma unroll
    for (int half = 0; half < 2; half++) {
        const int a = blk * 2 + half;
        ie_s[j] = idx_emb[a * D_MODEL + j];
        __syncthreads();
        float acc[NDEPTH];
#pragma unroll
        for (int m = 0; m < NDEPTH; m++) acc[m] = 0.f;
        float acci = 0.f;
        const float* Wde = W + (size_t)(512 + a * 768) * D_MODEL + j;
        const float* Wie = W + (size_t)(768 + a * 768) * D_MODEL + j;
#pragma unroll 8
        for (int k = 0; k < D_MODEL; k++) {
            float wde = Wde[k * D_MODEL];
            float wie = Wie[k * D_MODEL];
            acci = fmaf(ie_s[k], wie, acci);
#pragma unroll
            for (int m = 0; m < NDEPTH; m++)
                acc[m] = fmaf(de_s[m * D_MODEL + k], wde, acc[m]);
        }
#pragma unroll
        for (int m = 0; m < NDEPTH; m++)
            g_DPh[(a * NDEPTH + m) * D_MODEL + j] = __float2half_rn(acc[m] + acci);
        __syncthreads();
    }
    __threadfence();
    if (threadIdx.x == 0) atomicAdd(&g_done, 1);
}

__device__ void tp_body(int blk, char* sbuf,
                        const float* __restrict__ token_emb,
                        const float* __restrict__ W,
                        const float* __restrict__ bvec) {
    float* te_s = (float*)sbuf;  // 8*256
    const int j = threadIdx.x;
    const float bj = bvec[j];
    const float* Wt = W + j;

    for (int c = 0; c < 6; c++) {
        const int v0 = blk * 48 + c * 8;
        if (v0 >= VOCAB) break;
#pragma unroll
        for (int m = 0; m < 8; m++) {
            int v = v0 + m;
            te_s[m * D_MODEL + j] = (v < VOCAB) ? token_emb[v * D_MODEL + j] : 0.f;
        }
        __syncthreads();
        float acc[8];
#pragma unroll
        for (int m = 0; m < 8; m++) acc[m] = bj;
#pragma unroll 8
        for (int k = 0; k < D_MODEL; k++) {
            float wv = Wt[k * D_MODEL];
#pragma unroll
            for (int m = 0; m < 8; m++)
                acc[m] = fmaf(te_s[m * D_MODEL + k], wv, acc[m]);
        }
#pragma unroll
        for (int m = 0; m < 8; m++) {
            int v = v0 + m;
            if (v < VOCAB) g_TPh[v * D_MODEL + j] = __float2half_rn(acc[m]);
        }
        __syncthreads();
    }
    __threadfence();
    if (threadIdx.x == 0) atomicAdd(&g_done, 1);
}

__global__ __launch_bounds__(256, 2)
void mega_kernel(const float* __restrict__ ce,
                 const float* __restrict__ depth_emb,
                 const float* __restrict__ idx_emb,
                 const float* __restrict__ token_emb,
                 const float* __restrict__ W,
                 const float* __restrict__ bvec,
                 const int* __restrict__ nid,
                 const int* __restrict__ cdep,
                 const float* __restrict__ ln_g,
                 const float* __restrict__ ln_b,
                 float* __restrict__ out) {
    extern __shared__ char smem[];
    const int b = blockIdx.x;
    if (b < GEMM_BLOCKS) gemm_body(smem, b >> 1, b & 1, ce, nid, cdep, ln_g, ln_b, out);
    else if (b < GEMM_BLOCKS + DP_BLOCKS) dp_body(b - GEMM_BLOCKS, smem, depth_emb, idx_emb, W);
    else tp_body(b - GEMM_BLOCKS - DP_BLOCKS, smem, token_emb, W, bvec);
}

// --------------------------------- launch -------------------------------------
extern "C" void kernel_launch(void* const* d_in, const int* in_sizes, int n_in,
                              void* d_out, int out_size) {
    const int*   nid          = (const int*)d_in[0];
    const float* child_embs   = (const float*)d_in[1];
    const int*   child_depths = (const int*)d_in[2];
    const float* token_emb    = (const float*)d_in[3];
    const float* depth_emb    = (const float*)d_in[4];
    const float* idx_emb      = (const float*)d_in[5];
    const float* W            = (const float*)d_in[6];
    const float* bvec         = (const float*)d_in[7];
    const float* ln_g         = (const float*)d_in[8];
    const float* ln_b         = (const float*)d_in[9];
    float* out = (float*)d_out;

    cudaFuncSetAttribute(mega_kernel, cudaFuncAttributeMaxDynamicSharedMemorySize, SMEM_BYTES);

    convW_kernel<<<KTOT / 16, 256>>>(W);
    mega_kernel<<<GEMM_BLOCKS + DP_BLOCKS + TP_BLOCKS, 256, SMEM_BYTES>>>(
        child_embs, depth_emb, idx_emb, token_emb, W, bvec,
        nid, child_depths, ln_g, ln_b, out);
}

// round 12
// speedup vs baseline: 1.3539x; 1.1193x over previous
#include <cuda_runtime.h>
#include <cuda_fp16.h>
#include <cstdint>

#define D_MODEL 256
#define ARITY 32
#define NDEPTH 15
#define VOCAB 1027
#define BATCH 8192
#define KTOT 8192
#define LN_EPS 1e-5f

// ------------------------- device scratch (no allocs allowed) -----------------
__device__ __align__(16) __half g_TPh[VOCAB * D_MODEL];           // token proj + b (fp16)
__device__ __align__(16) __half g_DPh[ARITY * NDEPTH * D_MODEL];  // depth+idx proj (fp16)
// B pre-swizzled: chunk c (64 k) -> 32KB block: row n (0..255) x 128B, 16B units
// XOR-swizzled exactly as the GEMM smem image. g_WTsw[c*32768 + n*128 + (ko*16 ^ ((n&7)<<4))]
__device__ __align__(16) __half g_WTsw[(size_t)D_MODEL * KTOT];
__device__ __align__(16) float g_part[(size_t)BATCH * D_MODEL];   // split-K partials (kh=1)
__device__ int g_done;
__device__ int g_flag[128];

// ---------------- convW: convert+transpose W -> pre-swizzled fp16 blocks -------
__global__ __launch_bounds__(256)
void convW_kernel(const float* __restrict__ W) {
    if (threadIdx.x == 0) {
        if (blockIdx.x == 0) g_done = 0;
        if (blockIdx.x < 128) g_flag[blockIdx.x] = 0;
    }
    __shared__ float ws[16][257];
    const int kc = blockIdx.x * 16;   // 16 k-columns per block, kc multiple of 16
    const int t = threadIdx.x;        // output row n
#pragma unroll
    for (int r = 0; r < 16; r++) {
        int kg = kc + r;
        ws[r][t] = W[(size_t)(256 + (kg >> 8) * 768 + (kg & 255)) * D_MODEL + t];
    }
    __syncthreads();
    uint32_t hi[8];
#pragma unroll
    for (int p = 0; p < 8; p++) {
        __half2 h = __floats2half2_rn(ws[2 * p][t], ws[2 * p + 1][t]);
        hi[p] = *(uint32_t*)&h;
    }
    const int c  = kc >> 6;            // 64-k chunk id
    const int ko = (kc & 63) >> 3;     // 16B-unit index within row (even)
    char* base = (char*)g_WTsw + (size_t)c * 32768 + (size_t)t * 128;
    const uint32_t x = (uint32_t)((t & 7) << 4);
    *(uint4*)(base + (((uint32_t)(ko * 16)) ^ x))       = make_uint4(hi[0], hi[1], hi[2], hi[3]);
    *(uint4*)(base + (((uint32_t)((ko + 1) * 16)) ^ x)) = make_uint4(hi[4], hi[5], hi[6], hi[7]);
}

// ================================ mega kernel ==================================
// 256 threads/CTA. blocks [0,256): GEMM split-K (mt=b>>1, kh=b&1).
// blocks [256,272): dp (2 arities)   blocks [272,296): tp (48 vocab rows)
#define GEMM_BLOCKS 256
#define DP_BLOCKS 16
#define TP_BLOCKS 24
#define PREP_TOTAL (DP_BLOCKS + TP_BLOCKS)
#define SST 40960
#define BOFF 8192
#define MB0 81920
#define MB1 81928
#define SMEM_BYTES 81952

__device__ __forceinline__ void ldsm4(uint32_t* r, uint32_t a) {
    asm volatile("ldmatrix.sync.aligned.m8n8.x4.shared.b16 {%0,%1,%2,%3}, [%4];"
                 : "=r"(r[0]), "=r"(r[1]), "=r"(r[2]), "=r"(r[3]) : "r"(a));
}
__device__ __forceinline__ void mma_fp16(float* c, const uint32_t* a, const uint32_t* b) {
    asm volatile(
        "mma.sync.aligned.m16n8k16.row.col.f32.f16.f16.f32 "
        "{%0,%1,%2,%3}, {%4,%5,%6,%7}, {%8,%9}, {%0,%1,%2,%3};"
        : "+f"(c[0]), "+f"(c[1]), "+f"(c[2]), "+f"(c[3])
        : "r"(a[0]), "r"(a[1]), "r"(a[2]), "r"(a[3]), "r"(b[0]), "r"(b[1]));
}
__device__ __forceinline__ int ld_acq(const int* p) {
    int v;
    asm volatile("ld.acquire.gpu.s32 %0, [%1];" : "=r"(v) : "l"(p));
    return v;
}
__device__ __forceinline__ void mbar_init(uint32_t a, uint32_t cnt) {
    asm volatile("mbarrier.init.shared.b64 [%0], %1;" :: "r"(a), "r"(cnt) : "memory");
}
__device__ __forceinline__ void bulkB(uint32_t dst, const void* src, uint32_t mbar) {
    asm volatile("mbarrier.arrive.expect_tx.shared.b64 _, [%0], %1;"
                 :: "r"(mbar), "r"(32768u) : "memory");
    asm volatile("cp.async.bulk.shared::cluster.global.mbarrier::complete_tx::bytes "
                 "[%0], [%1], %2, [%3];"
                 :: "r"(dst), "l"(src), "r"(32768u), "r"(mbar) : "memory");
}
__device__ __forceinline__ void mbar_wait(uint32_t a, uint32_t parity) {
    asm volatile(
        "{\n\t.reg .pred P;\n\t"
        "LW_%=:\n\t"
        "mbarrier.try_wait.parity.acquire.cta.shared::cta.b64 P, [%0], %1, 0x989680;\n\t"
        "@P bra LD_%=;\n\t"
        "bra LW_%=;\n\t"
        "LD_%=:\n\t}"
        :: "r"(a), "r"(parity) : "memory");
}
__device__ __forceinline__ void add_half8(float* hb, uint4 v) {
    const __half2* q = (const __half2*)&v;
#pragma unroll
    for (int p = 0; p < 4; p++) {
        float2 f = __half22float2(q[p]);
        hb[2 * p] += f.x;
        hb[2 * p + 1] += f.y;
    }
}

__device__ void gemm_body(char* smem, int mt, int kh, const float* __restrict__ ce,
                          const int* __restrict__ nid, const int* __restrict__ cdep,
                          const float* __restrict__ ln_g, const float* __restrict__ ln_b,
                          float* __restrict__ out) {
    uint32_t sb;
    asm("{ .reg .u64 t; cvta.to.shared.u64 t, %1; cvt.u32.u64 %0, t; }"
        : "=r"(sb) : "l"(smem));
    const int t = threadIdx.x;
    const int lane = t & 31, w = t >> 5;
    const int wm = w & 1, wn = w >> 1;     // 2 x 4 warps; warp tile 32 x 64
    const int m0 = mt * 64;
    const int c0 = kh * 64;

    // A ldsm addressing
    const int arow0 = wm * 32 + (lane & 7) + ((lane >> 3) & 1) * 8;
    const uint32_t axor = (uint32_t)((arow0 & 7) << 4);
    const uint32_t khA = (uint32_t)((lane >> 4) * 16);
    // B ldsm addressing
    const int brow0 = wn * 64 + (lane & 7) + ((lane >> 4) & 1) * 8;
    const uint32_t bxor = (uint32_t)((lane & 7) << 4);
    const uint32_t khB = (uint32_t)(((lane >> 3) & 1) * 16);
    uint32_t arowb[2], browb[4];
#pragma unroll
    for (int i = 0; i < 2; i++) arowb[i] = (uint32_t)(arow0 + i * 16) * 128;
#pragma unroll
    for (int jp = 0; jp < 4; jp++) browb[jp] = (uint32_t)(brow0 + jp * 16) * 128;

    // A LDG/STS mapping
    const int prow = t >> 2, pcg = t & 3;
    const uint32_t prx = (uint32_t)((prow & 7) << 4);

    float acc[2][8][4];
#pragma unroll
    for (int i = 0; i < 2; i++)
#pragma unroll
        for (int j = 0; j < 8; j++)
#pragma unroll
            for (int q = 0; q < 4; q++) acc[i][j][q] = 0.f;

    float4 av[4];

    auto loadA = [&](int s) {
        const int c = c0 + s;
        const int a = c >> 2, kin = (c & 3) * 64;
        const float* p = ce + ((size_t)a * BATCH + m0 + prow) * D_MODEL + kin + pcg * 16;
#pragma unroll
        for (int q = 0; q < 4; q++) av[q] = *(const float4*)(p + q * 4);
    };
    auto stsA = [&](int buf) {
        const uint32_t da = sb + buf * SST;
        const uint32_t rbase = (uint32_t)prow * 128;
        uint32_t hv[8];
#pragma unroll
        for (int q = 0; q < 4; q++) {
            __half2 h01 = __floats2half2_rn(av[q].x, av[q].y);
            __half2 h23 = __floats2half2_rn(av[q].z, av[q].w);
            hv[2 * q]     = *(uint32_t*)&h01;
            hv[2 * q + 1] = *(uint32_t*)&h23;
        }
#pragma unroll
        for (int q = 0; q < 2; q++) {
            uint32_t off = rbase + (((uint32_t)(pcg * 32 + q * 16)) ^ prx);
            asm volatile("st.shared.v4.b32 [%0], {%1,%2,%3,%4};"
                         :: "r"(da + off), "r"(hv[4 * q]), "r"(hv[4 * q + 1]),
                            "r"(hv[4 * q + 2]), "r"(hv[4 * q + 3]));
        }
    };
    auto compute = [&](int buf) {
        const uint32_t SA = sb + buf * SST;
        const uint32_t SB = sb + buf * SST + BOFF;
#pragma unroll
        for (int kk = 0; kk < 4; kk++) {
            uint32_t ah[2][4], bh[4][4];
            const uint32_t ka = ((uint32_t)(kk * 32) + khA) ^ axor;
            const uint32_t kb = ((uint32_t)(kk * 32) + khB) ^ bxor;
#pragma unroll
            for (int i = 0; i < 2; i++) ldsm4(ah[i], SA + arowb[i] + ka);
#pragma unroll
            for (int jp = 0; jp < 4; jp++) ldsm4(bh[jp], SB + browb[jp] + kb);
#pragma unroll
            for (int i = 0; i < 2; i++)
#pragma unroll
                for (int j = 0; j < 8; j++)
                    mma_fp16(acc[i][j], ah[i], &bh[j >> 1][(j & 1) * 2]);
        }
    };

    // -------- prologue: mbars, bulk B(0)/B(1), A(0)/A(1) --------
    if (t == 0) { mbar_init(sb + MB0, 1); mbar_init(sb + MB1, 1); }
    __syncthreads();
    if (t == 0) {
        bulkB(sb + BOFF,       (const char*)g_WTsw + (size_t)(c0 + 0) * 32768, sb + MB0);
        bulkB(sb + SST + BOFF, (const char*)g_WTsw + (size_t)(c0 + 1) * 32768, sb + MB1);
    }
    loadA(0); stsA(0);
    loadA(1); stsA(1);
    __syncthreads();

    // -------- main loop: stage s computes buf s&1 --------
    for (int s = 0; s < 64; s++) {
        const int buf = s & 1;
        mbar_wait(sb + (buf ? MB1 : MB0), (uint32_t)((s >> 1) & 1));
        if (s + 2 < 64) loadA(s + 2);
        compute(buf);
        __syncthreads();  // all warps done reading buf (A and B)
        if (s + 2 < 64) {
            if (t == 0)
                bulkB(sb + buf * SST + BOFF,
                      (const char*)g_WTsw + (size_t)(c0 + s + 2) * 32768,
                      sb + (buf ? MB1 : MB0));
            stsA(buf);  // A(s+2) into same buf; visible via stage s+1's barrier
        }
    }

    if (kh == 1) {
        // ---------------- write partial, raise flag ----------------------------
#pragma unroll
        for (int i = 0; i < 2; i++)
#pragma unroll
            for (int j = 0; j < 8; j++) {
                const int r = m0 + wm * 32 + i * 16 + (lane >> 2);
                const int c = wn * 64 + j * 8 + (lane & 3) * 2;
                *(float2*)(g_part + (size_t)r * D_MODEL + c) =
                    make_float2(acc[i][j][0], acc[i][j][1]);
                *(float2*)(g_part + (size_t)(r + 8) * D_MODEL + c) =
                    make_float2(acc[i][j][2], acc[i][j][3]);
            }
        __syncthreads();
        __threadfence();
        if (t == 0) atomicAdd(&g_flag[mt], 1);
        return;
    }

    // ---------------- kh==0: fused epilogue ------------------------------------
    __syncthreads();
    float* sh = (float*)smem;  // [64][260]
    {
        const int rb = wm * 32 + (lane >> 2);
        const int cbase = wn * 64 + (lane & 3) * 2;
#pragma unroll
        for (int i = 0; i < 2; i++)
#pragma unroll
            for (int j = 0; j < 8; j++) {
                const int rr = rb + i * 16;
                const int cc = cbase + j * 8;
                sh[rr * 260 + cc]           = acc[i][j][0];
                sh[rr * 260 + cc + 1]       = acc[i][j][1];
                sh[(rr + 8) * 260 + cc]     = acc[i][j][2];
                sh[(rr + 8) * 260 + cc + 1] = acc[i][j][3];
            }
    }
    if (t == 0) {
        while (ld_acq(&g_done) < PREP_TOTAL) __nanosleep(64);
        while (ld_acq(&g_flag[mt]) == 0) __nanosleep(64);
    }
    __syncthreads();

    const int cb = lane * 8;
    float4 gg0 = *(const float4*)(ln_g + cb), gg1 = *(const float4*)(ln_g + cb + 4);
    float4 bb0 = *(const float4*)(ln_b + cb), bb1 = *(const float4*)(ln_b + cb + 4);
    const float gj[8] = {gg0.x, gg0.y, gg0.z, gg0.w, gg1.x, gg1.y, gg1.z, gg1.w};
    const float lj[8] = {bb0.x, bb0.y, bb0.z, bb0.w, bb1.x, bb1.y, bb1.z, bb1.w};

    int dvals[8];
#pragma unroll
    for (int q = 0; q < 8; q++)
        dvals[q] = cdep[(size_t)lane * BATCH + (m0 + w * 8 + q)];

#pragma unroll 2
    for (int q = 0; q < 8; q++) {
        const int r = m0 + w * 8 + q;
        float hb[8];
        const float* sp = sh + (w * 8 + q) * 260 + cb;
#pragma unroll
        for (int x = 0; x < 8; x++) hb[x] = sp[x];

        {
            float4 p0 = *(const float4*)(g_part + (size_t)r * D_MODEL + cb);
            float4 p1 = *(const float4*)(g_part + (size_t)r * D_MODEL + cb + 4);
            hb[0] += p0.x; hb[1] += p0.y; hb[2] += p0.z; hb[3] += p0.w;
            hb[4] += p1.x; hb[5] += p1.y; hb[6] += p1.z; hb[7] += p1.w;
        }

        const int tk = nid[r];
        add_half8(hb, *(const uint4*)(g_TPh + tk * D_MODEL + cb));
#pragma unroll
        for (int a = 0; a < ARITY; a++) {
            const int d = __shfl_sync(0xFFFFFFFFu, dvals[q], a);
            add_half8(hb, *(const uint4*)(g_DPh + ((a * NDEPTH + d) << 8) + cb));
        }

        float s = 0.f, ss = 0.f;
#pragma unroll
        for (int x = 0; x < 8; x++) {
            hb[x] = fmaxf(hb[x], 0.f);
            s += hb[x];
            ss = fmaf(hb[x], hb[x], ss);
        }
#pragma unroll
        for (int o = 16; o > 0; o >>= 1) {
            s  += __shfl_xor_sync(0xFFFFFFFFu, s, o);
            ss += __shfl_xor_sync(0xFFFFFFFFu, ss, o);
        }
        const float mu = s * (1.f / 256.f);
        const float rs = rsqrtf(ss * (1.f / 256.f) - mu * mu + LN_EPS);

        float4 o0, o1;
        o0.x = (hb[0] - mu) * rs * gj[0] + lj[0];
        o0.y = (hb[1] - mu) * rs * gj[1] + lj[1];
        o0.z = (hb[2] - mu) * rs * gj[2] + lj[2];
        o0.w = (hb[3] - mu) * rs * gj[3] + lj[3];
        o1.x = (hb[4] - mu) * rs * gj[4] + lj[4];
        o1.y = (hb[5] - mu) * rs * gj[5] + lj[5];
        o1.z = (hb[6] - mu) * rs * gj[6] + lj[6];
        o1.w = (hb[7] - mu) * rs * gj[7] + lj[7];
        *(float4*)(out + (size_t)r * D_MODEL + cb)     = o0;
        *(float4*)(out + (size_t)r * D_MODEL + cb + 4) = o1;
    }
}

// ---------------- prep bodies (256 threads; packed into 40 blocks) -------------
__device__ void dp_body(int blk, char* sbuf,
                        const float* __restrict__ depth_emb,
                        const float* __restrict__ idx_emb,
                        const float* __restrict__ W) {
    float* de_s = (float*)sbuf;
    float* ie_s = de_s + NDEPTH * D_MODEL;
    const int j = threadIdx.x;
    for (int i = j; i < NDEPTH * D_MODEL; i += 256) de_s[i] = depth_emb[i];
    __syncthreads();

#pragma unroll
    for (int half = 0; half < 2; half++) {
        const int a = blk * 2 + half;
        ie_s[j] = idx_emb[a * D_MODEL + j];
        __syncthreads();
        float acc[NDEPTH];
#pragma unroll
        for (int m = 0; m < NDEPTH; m++) acc[m] = 0.f;
        float acci = 0.f;
        const float* Wde = W + (size_t)(512 + a * 768) * D_MODEL + j;
        const float* Wie = W + (size_t)(768 + a * 768) * D_MODEL + j;
#pragma unroll 8
        for (int k = 0; k < D_MODEL; k++) {
            float wde = Wde[k * D_MODEL];
            float wie = Wie[k * D_MODEL];
            acci = fmaf(ie_s[k], wie, acci);
#pragma unroll
            for (int m = 0; m < NDEPTH; m++)
                acc[m] = fmaf(de_s[m * D_MODEL + k], wde, acc[m]);
        }
#pragma unroll
        for (int m = 0; m < NDEPTH; m++)
            g_DPh[(a * NDEPTH + m) * D_MODEL + j] = __float2half_rn(acc[m] + acci);
        __syncthreads();
    }
    __threadfence();
    if (threadIdx.x == 0) atomicAdd(&g_done, 1);
}

__device__ void tp_body(int blk, char* sbuf,
                        const float* __restrict__ token_emb,
                        const float* __restrict__ W,
                        const float* __restrict__ bvec) {
    float* te_s = (float*)sbuf;
    const int j = threadIdx.x;
    const float bj = bvec[j];
    const float* Wt = W + j;

    for (int c = 0; c < 6; c++) {
        const int v0 = blk * 48 + c * 8;
        if (v0 >= VOCAB) break;
#pragma unroll
        for (int m = 0; m < 8; m++) {
            int v = v0 + m;
            te_s[m * D_MODEL + j] = (v < VOCAB) ? token_emb[v * D_MODEL + j] : 0.f;
        }
        __syncthreads();
        float acc[8];
#pragma unroll
        for (int m = 0; m < 8; m++) acc[m] = bj;
#pragma unroll 8
        for (int k = 0; k < D_MODEL; k++) {
            float wv = Wt[k * D_MODEL];
#pragma unroll
            for (int m = 0; m < 8; m++)
                acc[m] = fmaf(te_s[m * D_MODEL + k], wv, acc[m]);
        }
#pragma unroll
        for (int m = 0; m < 8; m++) {
            int v = v0 + m;
            if (v < VOCAB) g_TPh[v * D_MODEL + j] = __float2half_rn(acc[m]);
        }
        __syncthreads();
    }
    __threadfence();
    if (threadIdx.x == 0) atomicAdd(&g_done, 1);
}

__global__ __launch_bounds__(256, 2)
void mega_kernel(const float* __restrict__ ce,
                 const float* __restrict__ depth_emb,
                 const float* __restrict__ idx_emb,
                 const float* __restrict__ token_emb,
                 const float* __restrict__ W,
                 const float* __restrict__ bvec,
                 const int* __restrict__ nid,
                 const int* __restrict__ cdep,
                 const float* __restrict__ ln_g,
                 const float* __restrict__ ln_b,
                 float* __restrict__ out) {
    extern __shared__ char smem[];
    const int b = blockIdx.x;
    if (b < GEMM_BLOCKS) gemm_body(smem, b >> 1, b & 1, ce, nid, cdep, ln_g, ln_b, out);
    else if (b < GEMM_BLOCKS + DP_BLOCKS) dp_body(b - GEMM_BLOCKS, smem, depth_emb, idx_emb, W);
    else tp_body(b - GEMM_BLOCKS - DP_BLOCKS, smem, token_emb, W, bvec);
}

// --------------------------------- launch -------------------------------------
extern "C" void kernel_launch(void* const* d_in, const int* in_sizes, int n_in,
                              void* d_out, int out_size) {
    const int*   nid          = (const int*)d_in[0];
    const float* child_embs   = (const float*)d_in[1];
    const int*   child_depths = (const int*)d_in[2];
    const float* token_emb    = (const float*)d_in[3];
    const float* depth_emb    = (const float*)d_in[4];
    const float* idx_emb      = (const float*)d_in[5];
    const float* W            = (const float*)d_in[6];
    const float* bvec         = (const float*)d_in[7];
    const float* ln_g         = (const float*)d_in[8];
    const float* ln_b         = (const float*)d_in[9];
    float* out = (float*)d_out;

    cudaFuncSetAttribute(mega_kernel, cudaFuncAttributeMaxDynamicSharedMemorySize, SMEM_BYTES);

    convW_kernel<<<KTOT / 16, 256>>>(W);
    mega_kernel<<<GEMM_BLOCKS + DP_BLOCKS + TP_BLOCKS, 256, SMEM_BYTES>>>(
        child_embs, depth_emb, idx_emb, token_emb, W, bvec,
        nid, child_depths, ln_g, ln_b, out);
}

// round 13
// speedup vs baseline: 1.4396x; 1.0633x over previous
#include <cuda_runtime.h>
#include <cuda_fp16.h>
#include <cstdint>

#define D_MODEL 256
#define ARITY 32
#define NDEPTH 15
#define VOCAB 1027
#define BATCH 8192
#define KTOT 8192
#define LN_EPS 1e-5f

// ------------------------- device scratch (no allocs allowed) -----------------
__device__ __align__(16) __half g_TPh[VOCAB * D_MODEL];           // token proj + b (fp16)
__device__ __align__(16) __half g_DPh[ARITY * NDEPTH * D_MODEL];  // depth+idx proj (fp16)
// B pre-swizzled: chunk c (64 k) -> 32KB block, exact GEMM smem image
__device__ __align__(16) __half g_WTsw[(size_t)D_MODEL * KTOT];
__device__ __align__(16) float g_part[(size_t)BATCH * D_MODEL];   // split-K partials
__device__ int g_done;
__device__ int g_flag[256];   // per (tile, kh)

// ---------------- convW: convert+transpose W -> pre-swizzled fp16 blocks -------
__global__ __launch_bounds__(256)
void convW_kernel(const float* __restrict__ W) {
    if (threadIdx.x == 0) {
        if (blockIdx.x == 0) g_done = 0;
        if (blockIdx.x < 256) g_flag[blockIdx.x] = 0;
    }
    __shared__ float ws[16][257];
    const int kc = blockIdx.x * 16;
    const int t = threadIdx.x;        // output row n
#pragma unroll
    for (int r = 0; r < 16; r++) {
        int kg = kc + r;
        ws[r][t] = W[(size_t)(256 + (kg >> 8) * 768 + (kg & 255)) * D_MODEL + t];
    }
    __syncthreads();
    uint32_t hi[8];
#pragma unroll
    for (int p = 0; p < 8; p++) {
        __half2 h = __floats2half2_rn(ws[2 * p][t], ws[2 * p + 1][t]);
        hi[p] = *(uint32_t*)&h;
    }
    const int c  = kc >> 6;
    const int ko = (kc & 63) >> 3;
    char* base = (char*)g_WTsw + (size_t)c * 32768 + (size_t)t * 128;
    const uint32_t x = (uint32_t)((t & 7) << 4);
    *(uint4*)(base + (((uint32_t)(ko * 16)) ^ x))       = make_uint4(hi[0], hi[1], hi[2], hi[3]);
    *(uint4*)(base + (((uint32_t)((ko + 1) * 16)) ^ x)) = make_uint4(hi[4], hi[5], hi[6], hi[7]);
}

// ================================ mega kernel ==================================
#define GEMM_BLOCKS 256
#define DP_BLOCKS 16
#define TP_BLOCKS 24
#define PREP_TOTAL (DP_BLOCKS + TP_BLOCKS)
#define SST 40960
#define BOFF 8192
#define MB0 81920
#define MB1 81928
#define SMEM_BYTES 81952

__device__ __forceinline__ void ldsm4(uint32_t* r, uint32_t a) {
    asm volatile("ldmatrix.sync.aligned.m8n8.x4.shared.b16 {%0,%1,%2,%3}, [%4];"
                 : "=r"(r[0]), "=r"(r[1]), "=r"(r[2]), "=r"(r[3]) : "r"(a));
}
__device__ __forceinline__ void mma_fp16(float* c, const uint32_t* a, const uint32_t* b) {
    asm volatile(
        "mma.sync.aligned.m16n8k16.row.col.f32.f16.f16.f32 "
        "{%0,%1,%2,%3}, {%4,%5,%6,%7}, {%8,%9}, {%0,%1,%2,%3};"
        : "+f"(c[0]), "+f"(c[1]), "+f"(c[2]), "+f"(c[3])
        : "r"(a[0]), "r"(a[1]), "r"(a[2]), "r"(a[3]), "r"(b[0]), "r"(b[1]));
}
__device__ __forceinline__ int ld_acq(const int* p) {
    int v;
    asm volatile("ld.acquire.gpu.s32 %0, [%1];" : "=r"(v) : "l"(p));
    return v;
}
__device__ __forceinline__ void mbar_init(uint32_t a, uint32_t cnt) {
    asm volatile("mbarrier.init.shared.b64 [%0], %1;" :: "r"(a), "r"(cnt) : "memory");
}
__device__ __forceinline__ void bulkB(uint32_t dst, const void* src, uint32_t mbar) {
    asm volatile("mbarrier.arrive.expect_tx.shared.b64 _, [%0], %1;"
                 :: "r"(mbar), "r"(32768u) : "memory");
    asm volatile("cp.async.bulk.shared::cluster.global.mbarrier::complete_tx::bytes "
                 "[%0], [%1], %2, [%3];"
                 :: "r"(dst), "l"(src), "r"(32768u), "r"(mbar) : "memory");
}
__device__ __forceinline__ void mbar_wait(uint32_t a, uint32_t parity) {
    asm volatile(
        "{\n\t.reg .pred P;\n\t"
        "LW_%=:\n\t"
        "mbarrier.try_wait.parity.acquire.cta.shared::cta.b64 P, [%0], %1, 0x989680;\n\t"
        "@P bra LD_%=;\n\t"
        "bra LW_%=;\n\t"
        "LD_%=:\n\t}"
        :: "r"(a), "r"(parity) : "memory");
}
__device__ __forceinline__ void add_half8(float* hb, uint4 v) {
    const __half2* q = (const __half2*)&v;
#pragma unroll
    for (int p = 0; p < 4; p++) {
        float2 f = __half22float2(q[p]);
        hb[2 * p] += f.x;
        hb[2 * p + 1] += f.y;
    }
}

__device__ void gemm_body(char* smem, int mt, int kh, const float* __restrict__ ce,
                          const int* __restrict__ nid, const int* __restrict__ cdep,
                          const float* __restrict__ ln_g, const float* __restrict__ ln_b,
                          float* __restrict__ out) {
    uint32_t sb;
    asm("{ .reg .u64 t; cvta.to.shared.u64 t, %1; cvt.u32.u64 %0, t; }"
        : "=r"(sb) : "l"(smem));
    const int t = threadIdx.x;
    const int lane = t & 31, w = t >> 5;
    const int wm = w & 1, wn = w >> 1;     // 2 x 4 warps; warp tile 32 x 64
    const int m0 = mt * 64;
    const int c0 = kh * 64;

    // A ldsm addressing
    const int arow0 = wm * 32 + (lane & 7) + ((lane >> 3) & 1) * 8;
    const uint32_t axor = (uint32_t)((arow0 & 7) << 4);
    const uint32_t khA = (uint32_t)((lane >> 4) * 16);
    // B ldsm addressing
    const int brow0 = wn * 64 + (lane & 7) + ((lane >> 4) & 1) * 8;
    const uint32_t bxor = (uint32_t)((lane & 7) << 4);
    const uint32_t khB = (uint32_t)(((lane >> 3) & 1) * 16);
    uint32_t arowb[2], browb[4];
#pragma unroll
    for (int i = 0; i < 2; i++) arowb[i] = (uint32_t)(arow0 + i * 16) * 128;
#pragma unroll
    for (int jp = 0; jp < 4; jp++) browb[jp] = (uint32_t)(brow0 + jp * 16) * 128;

    // A LDG/STS mapping
    const int prow = t >> 2, pcg = t & 3;
    const uint32_t prx = (uint32_t)((prow & 7) << 4);

    float acc[2][8][4];
#pragma unroll
    for (int i = 0; i < 2; i++)
#pragma unroll
        for (int j = 0; j < 8; j++)
#pragma unroll
            for (int q = 0; q < 4; q++) acc[i][j][q] = 0.f;

    float4 av[4];

    auto loadA = [&](int s) {
        const int c = c0 + s;
        const int a = c >> 2, kin = (c & 3) * 64;
        const float* p = ce + ((size_t)a * BATCH + m0 + prow) * D_MODEL + kin + pcg * 16;
#pragma unroll
        for (int q = 0; q < 4; q++) av[q] = *(const float4*)(p + q * 4);
    };
    auto stsA = [&](int buf) {
        const uint32_t da = sb + buf * SST;
        const uint32_t rbase = (uint32_t)prow * 128;
        uint32_t hv[8];
#pragma unroll
        for (int q = 0; q < 4; q++) {
            __half2 h01 = __floats2half2_rn(av[q].x, av[q].y);
            __half2 h23 = __floats2half2_rn(av[q].z, av[q].w);
            hv[2 * q]     = *(uint32_t*)&h01;
            hv[2 * q + 1] = *(uint32_t*)&h23;
        }
#pragma unroll
        for (int q = 0; q < 2; q++) {
            uint32_t off = rbase + (((uint32_t)(pcg * 32 + q * 16)) ^ prx);
            asm volatile("st.shared.v4.b32 [%0], {%1,%2,%3,%4};"
                         :: "r"(da + off), "r"(hv[4 * q]), "r"(hv[4 * q + 1]),
                            "r"(hv[4 * q + 2]), "r"(hv[4 * q + 3]));
        }
    };
    auto compute = [&](int buf) {
        const uint32_t SA = sb + buf * SST;
        const uint32_t SB = sb + buf * SST + BOFF;
#pragma unroll
        for (int kk = 0; kk < 4; kk++) {
            uint32_t ah[2][4], bh[4][4];
            const uint32_t ka = ((uint32_t)(kk * 32) + khA) ^ axor;
            const uint32_t kb = ((uint32_t)(kk * 32) + khB) ^ bxor;
#pragma unroll
            for (int i = 0; i < 2; i++) ldsm4(ah[i], SA + arowb[i] + ka);
#pragma unroll
            for (int jp = 0; jp < 4; jp++) ldsm4(bh[jp], SB + browb[jp] + kb);
#pragma unroll
            for (int i = 0; i < 2; i++)
#pragma unroll
                for (int j = 0; j < 8; j++)
                    mma_fp16(acc[i][j], ah[i], &bh[j >> 1][(j & 1) * 2]);
        }
    };

    // -------- prologue --------
    if (t == 0) { mbar_init(sb + MB0, 1); mbar_init(sb + MB1, 1); }
    __syncthreads();
    if (t == 0) {
        bulkB(sb + BOFF,       (const char*)g_WTsw + (size_t)(c0 + 0) * 32768, sb + MB0);
        bulkB(sb + SST + BOFF, (const char*)g_WTsw + (size_t)(c0 + 1) * 32768, sb + MB1);
    }
    loadA(0); stsA(0);
    loadA(1); stsA(1);
    if (t == 0) mbar_wait(sb + MB0, 0);   // B(0) ready (leader-only)
    __syncthreads();

    // -------- main loop: compute s; leader waits B(s+1) before stage barrier ----
    for (int s = 0; s < 64; s++) {
        const int buf = s & 1;
        if (s + 2 < 64) loadA(s + 2);
        compute(buf);
        if (t == 0 && s + 1 < 64)
            mbar_wait(sb + (buf ? MB0 : MB1), (uint32_t)(((s + 1) >> 1) & 1));
        __syncthreads();  // buf fully read by all; B(s+1) visible to all
        if (s + 2 < 64) {
            if (t == 0)
                bulkB(sb + buf * SST + BOFF,
                      (const char*)g_WTsw + (size_t)(c0 + s + 2) * 32768,
                      sb + (buf ? MB1 : MB0));
            stsA(buf);  // A(s+2); readers separated by next stage's barrier
        }
    }

    // ---------------- symmetric epilogue: each CTA owns 32 rows -----------------
    // owned rows: [m0 + kh*32, m0 + kh*32 + 32). warps wm==kh stage acc -> smem;
    // warps wm!=kh write acc -> g_part (partner's owned rows).
    float* sh = (float*)smem;  // [32][260]
    if (wm == kh) {
        const int rb = lane >> 2;                 // local row within half
        const int cbase = wn * 64 + (lane & 3) * 2;
#pragma unroll
        for (int i = 0; i < 2; i++)
#pragma unroll
            for (int j = 0; j < 8; j++) {
                const int rr = i * 16 + rb;
                const int cc = cbase + j * 8;
                sh[rr * 260 + cc]           = acc[i][j][0];
                sh[rr * 260 + cc + 1]       = acc[i][j][1];
                sh[(rr + 8) * 260 + cc]     = acc[i][j][2];
                sh[(rr + 8) * 260 + cc + 1] = acc[i][j][3];
            }
    } else {
#pragma unroll
        for (int i = 0; i < 2; i++)
#pragma unroll
            for (int j = 0; j < 8; j++) {
                const int r = m0 + wm * 32 + i * 16 + (lane >> 2);
                const int c = wn * 64 + j * 8 + (lane & 3) * 2;
                *(float2*)(g_part + (size_t)r * D_MODEL + c) =
                    make_float2(acc[i][j][0], acc[i][j][1]);
                *(float2*)(g_part + (size_t)(r + 8) * D_MODEL + c) =
                    make_float2(acc[i][j][2], acc[i][j][3]);
            }
    }
    __syncthreads();
    __threadfence();
    if (t == 0) {
        atomicAdd(&g_flag[2 * mt + kh], 1);                       // my partial ready
        while (ld_acq(&g_done) < PREP_TOTAL) __nanosleep(64);      // tables ready
        while (ld_acq(&g_flag[2 * mt + (1 - kh)]) == 0) __nanosleep(64);  // partner partial
    }
    __syncthreads();

    // epilogue over 32 owned rows: warp w handles 4 rows
    const int cb = lane * 8;
    float4 gg0 = *(const float4*)(ln_g + cb), gg1 = *(const float4*)(ln_g + cb + 4);
    float4 bb0 = *(const float4*)(ln_b + cb), bb1 = *(const float4*)(ln_b + cb + 4);
    const float gj[8] = {gg0.x, gg0.y, gg0.z, gg0.w, gg1.x, gg1.y, gg1.z, gg1.w};
    const float lj[8] = {bb0.x, bb0.y, bb0.z, bb0.w, bb1.x, bb1.y, bb1.z, bb1.w};
    const int rbase = m0 + kh * 32 + w * 4;

    int dvals[4];
#pragma unroll
    for (int q = 0; q < 4; q++)
        dvals[q] = cdep[(size_t)lane * BATCH + (rbase + q)];

#pragma unroll
    for (int q = 0; q < 4; q++) {
        const int r = rbase + q;
        float hb[8];
        const float* sp = sh + (w * 4 + q) * 260 + cb;
#pragma unroll
        for (int x = 0; x < 8; x++) hb[x] = sp[x];

        {   // partner's K-half partial
            float4 p0 = *(const float4*)(g_part + (size_t)r * D_MODEL + cb);
            float4 p1 = *(const float4*)(g_part + (size_t)r * D_MODEL + cb + 4);
            hb[0] += p0.x; hb[1] += p0.y; hb[2] += p0.z; hb[3] += p0.w;
            hb[4] += p1.x; hb[5] += p1.y; hb[6] += p1.z; hb[7] += p1.w;
        }

        const int tk = nid[r];
        add_half8(hb, *(const uint4*)(g_TPh + tk * D_MODEL + cb));
#pragma unroll
        for (int a = 0; a < ARITY; a++) {
            const int d = __shfl_sync(0xFFFFFFFFu, dvals[q], a);
            add_half8(hb, *(const uint4*)(g_DPh + ((a * NDEPTH + d) << 8) + cb));
        }

        float s = 0.f, ss = 0.f;
#pragma unroll
        for (int x = 0; x < 8; x++) {
            hb[x] = fmaxf(hb[x], 0.f);
            s += hb[x];
            ss = fmaf(hb[x], hb[x], ss);
        }
#pragma unroll
        for (int o = 16; o > 0; o >>= 1) {
            s  += __shfl_xor_sync(0xFFFFFFFFu, s, o);
            ss += __shfl_xor_sync(0xFFFFFFFFu, ss, o);
        }
        const float mu = s * (1.f / 256.f);
        const float rs = rsqrtf(ss * (1.f / 256.f) - mu * mu + LN_EPS);

        float4 o0, o1;
        o0.x = (hb[0] - mu) * rs * gj[0] + lj[0];
        o0.y = (hb[1] - mu) * rs * gj[1] + lj[1];
        o0.z = (hb[2] - mu) * rs * gj[2] + lj[2];
        o0.w = (hb[3] - mu) * rs * gj[3] + lj[3];
        o1.x = (hb[4] - mu) * rs * gj[4] + lj[4];
        o1.y = (hb[5] - mu) * rs * gj[5] + lj[5];
        o1.z = (hb[6] - mu) * rs * gj[6] + lj[6];
        o1.w = (hb[7] - mu) * rs * gj[7] + lj[7];
        *(float4*)(out + (size_t)r * D_MODEL + cb)     = o0;
        *(float4*)(out + (size_t)r * D_MODEL + cb + 4) = o1;
    }
}

// ---------------- prep bodies (256 threads; packed into 40 blocks) -------------
__device__ void dp_body(int blk, char* sbuf,
                        const float* __restrict__ depth_emb,
                        const float* __restrict__ idx_emb,
                        const float* __restrict__ W) {
    float* de_s = (float*)sbuf;
    float* ie_s = de_s + NDEPTH * D_MODEL;
    const int j = threadIdx.x;
    for (int i = j; i < NDEPTH * D_MODEL; i += 256) de_s[i] = depth_emb[i];
    __syncthreads();

#pragma unroll
    for (int half = 0; half < 2; half++) {
        const int a = blk * 2 + half;
        ie_s[j] = idx_emb[a * D_MODEL + j];
        __syncthreads();
        float acc[NDEPTH];
#pragma unroll
        for (int m = 0; m < NDEPTH; m++) acc[m] = 0.f;
        float acci = 0.f;
        const float* Wde = W + (size_t)(512 + a * 768) * D_MODEL + j;
        const float* Wie = W + (size_t)(768 + a * 768) * D_MODEL + j;
#pragma unroll 8
        for (int k = 0; k < D_MODEL; k++) {
            float wde = Wde[k * D_MODEL];
            float wie = Wie[k * D_MODEL];
            acci = fmaf(ie_s[k], wie, acci);
#pragma unroll
            for (int m = 0; m < NDEPTH; m++)
                acc[m] = fmaf(de_s[m * D_MODEL + k], wde, acc[m]);
        }
#pragma unroll
        for (int m = 0; m < NDEPTH; m++)
            g_DPh[(a * NDEPTH + m) * D_MODEL + j] = __float2half_rn(acc[m] + acci);
        __syncthreads();
    }
    __threadfence();
    if (threadIdx.x == 0) atomicAdd(&g_done, 1);
}

__device__ void tp_body(int blk, char* sbuf,
                        const float* __restrict__ token_emb,
                        const float* __restrict__ W,
                        const float* __restrict__ bvec) {
    float* te_s = (float*)sbuf;
    const int j = threadIdx.x;
    const float bj = bvec[j];
    const float* Wt = W + j;

    for (int c = 0; c < 6; c++) {
        const int v0 = blk * 48 + c * 8;
        if (v0 >= VOCAB) break;
#pragma unroll
        for (int m = 0; m < 8; m++) {
            int v = v0 + m;
            te_s[m * D_MODEL + j] = (v < VOCAB) ? token_emb[v * D_MODEL + j] : 0.f;
        }
        __syncthreads();
        float acc[8];
#pragma unroll
        for (int m = 0; m < 8; m++) acc[m] = bj;
#pragma unroll 8
        for (int k = 0; k < D_MODEL; k++) {
            float wv = Wt[k * D_MODEL];
#pragma unroll
            for (int m = 0; m < 8; m++)
                acc[m] = fmaf(te_s[m * D_MODEL + k], wv, acc[m]);
        }
#pragma unroll
        for (int m = 0; m < 8; m++) {
            int v = v0 + m;
            if (v < VOCAB) g_TPh[v * D_MODEL + j] = __float2half_rn(acc[m]);
        }
        __syncthreads();
    }
    __threadfence();
    if (threadIdx.x == 0) atomicAdd(&g_done, 1);
}

__global__ __launch_bounds__(256, 2)
void mega_kernel(const float* __restrict__ ce,
                 const float* __restrict__ depth_emb,
                 const float* __restrict__ idx_emb,
                 const float* __restrict__ token_emb,
                 const float* __restrict__ W,
                 const float* __restrict__ bvec,
                 const int* __restrict__ nid,
                 const int* __restrict__ cdep,
                 const float* __restrict__ ln_g,
                 const float* __restrict__ ln_b,
                 float* __restrict__ out) {
    extern __shared__ char smem[];
    const int b = blockIdx.x;
    if (b < GEMM_BLOCKS) gemm_body(smem, b >> 1, b & 1, ce, nid, cdep, ln_g, ln_b, out);
    else if (b < GEMM_BLOCKS + DP_BLOCKS) dp_body(b - GEMM_BLOCKS, smem, depth_emb, idx_emb, W);
    else tp_body(b - GEMM_BLOCKS - DP_BLOCKS, smem, token_emb, W, bvec);
}

// --------------------------------- launch -------------------------------------
extern "C" void kernel_launch(void* const* d_in, const int* in_sizes, int n_in,
                              void* d_out, int out_size) {
    const int*   nid          = (const int*)d_in[0];
    const float* child_embs   = (const float*)d_in[1];
    const int*   child_depths = (const int*)d_in[2];
    const float* token_emb    = (const float*)d_in[3];
    const float* depth_emb    = (const float*)d_in[4];
    const float* idx_emb      = (const float*)d_in[5];
    const float* W            = (const float*)d_in[6];
    const float* bvec         = (const float*)d_in[7];
    const float* ln_g         = (const float*)d_in[8];
    const float* ln_b         = (const float*)d_in[9];
    float* out = (float*)d_out;

    cudaFuncSetAttribute(mega_kernel, cudaFuncAttributeMaxDynamicSharedMemorySize, SMEM_BYTES);

    convW_kernel<<<KTOT / 16, 256>>>(W);
    mega_kernel<<<GEMM_BLOCKS + DP_BLOCKS + TP_BLOCKS, 256, SMEM_BYTES>>>(
        child_embs, depth_emb, idx_emb, token_emb, W, bvec,
        nid, child_depths, ln_g, ln_b, out);
}